// round 13
// baseline (speedup 1.0000x reference)
#include <cuda_runtime.h>
#include <cuda_fp16.h>

#define RES     256
#define CHOUT   16
#define NCH     128          // CH*RR phasor channels per plane
#define NPTS    262144
#define HPTS    131072
#define PI_F    3.14159265358979323846f

// Scratch (device globals: allocation-free rule)
// g_mid layout: [x][ky][ch]  (x<256, ky<128, ch<128), complex fp16, 16.7 MB
__device__ __half2 g_mid[256 * 128 * NCH];
// feat ping-pong: [y][x][256ch] fp16 unnormalized, 2 x 33.5 MB
__device__ __half  g_feat[2][RES * RES * 2 * NCH];

__device__ __forceinline__ float2 cadd(float2 a, float2 b) { return make_float2(a.x + b.x, a.y + b.y); }
__device__ __forceinline__ float2 csub(float2 a, float2 b) { return make_float2(a.x - b.x, a.y - b.y); }
__device__ __forceinline__ float2 cmul(float2 a, float2 b) {
    return make_float2(fmaf(a.x, b.x, -a.y * b.y), fmaf(a.x, b.y, a.y * b.x));
}
__device__ __forceinline__ float2 muli(float2 a) { return make_float2(-a.y, a.x); }

// ===========================================================================
// Register DFT-16 (inverse, +i), radix-4 x radix-4, natural-order output.
// (verbatim from R12)
// ===========================================================================
__device__ __forceinline__ float2 w16m(int k) {
    const float C1 = 0.9238795325112867f, S1 = 0.3826834323650898f;
    const float C2 = 0.7071067811865476f;
    switch (k) {
        case 0:  return make_float2( 1.f, 0.f);
        case 1:  return make_float2( C1,  S1);
        case 2:  return make_float2( C2,  C2);
        case 3:  return make_float2( S1,  C1);
        case 4:  return make_float2( 0.f, 1.f);
        case 6:  return make_float2(-C2,  C2);
        default: return make_float2(-C1, -S1);     // case 9
    }
}

__device__ __forceinline__ void dft4i(float2& x0, float2& x1, float2& x2, float2& x3) {
    float2 a = cadd(x0, x2), b = csub(x0, x2);
    float2 c = cadd(x1, x3), d = muli(csub(x1, x3));
    x0 = cadd(a, c); x1 = cadd(b, d); x2 = csub(a, c); x3 = csub(b, d);
}

__device__ __forceinline__ void dft16_tail(float2 d[16], float2 out[16]) {
#pragma unroll
    for (int m = 0; m < 4; m++) {
        float2 e0 = d[0 + 4 * m];
        float2 e1 = cmul(d[1 + 4 * m], w16m(1 * m));
        float2 e2 = cmul(d[2 + 4 * m], w16m(2 * m));
        float2 e3 = cmul(d[3 + 4 * m], w16m(3 * m));
        float2 A = cadd(e0, e2), B = csub(e0, e2);
        float2 C = cadd(e1, e3), D = muli(csub(e1, e3));
        out[m]      = cadd(A, C);
        out[m + 4]  = cadd(B, D);
        out[m + 8]  = csub(A, C);
        out[m + 12] = csub(B, D);
    }
}

__device__ __forceinline__ void dft16_full(float2 x[16], float2 out[16]) {
#pragma unroll
    for (int a = 0; a < 4; a++) dft4i(x[a], x[a + 4], x[a + 8], x[a + 12]);
    dft16_tail(x, out);
}

__device__ __forceinline__ void dft16_half(const float2 x[8], float2 out[16]) {
    float2 d[16];
#pragma unroll
    for (int a = 0; a < 4; a++) {
        float2 u = x[a], v = x[a + 4];
        float2 iv = muli(v);
        d[a]      = cadd(u, v);
        d[a + 4]  = cadd(u, iv);
        d[a + 8]  = csub(u, v);
        d[a + 12] = csub(u, iv);
    }
    dft16_tail(d, out);
}

// ===========================================================================
// Heterogeneous-slot kernel. Blocks [0, fft_nblk): FFT role (mode 1 = x-pass,
// mode 2 = y-pass into g_feat[fw]); remaining blocks: sample g_feat[fr] for
// points [samp_base, samp_base + samp_npts). FFT bodies and sampler body are
// the R12 kernels verbatim; the 34.9KB static smem does not reduce sampler
// occupancy (sampler is register-limited to ~6 blocks/SM anyway).
// ===========================================================================
__global__ void __launch_bounds__(256)
kslot(const float* __restrict__ P, int fft_mode, int fft_nblk, int fw, int fr,
      const float* __restrict__ inputs, float* __restrict__ out,
      int ix, int iy, int is, int accum, int samp_base, int samp_npts) {
    __shared__ float2 sbuf[16 * 273];              // FFT transpose buffer
    int tid = threadIdx.x;

    if ((int)blockIdx.x < fft_nblk) {
        // ===================== FFT role =====================
        int bid = blockIdx.x;
        int g = bid & 7, slice = bid >> 3;         // slice = ky (m1) / xcol (m2)

        // --- phase 1 ---
        float2 A[16];
        {
            float2 x[8];
            if (fft_mode == 1) {
                int n1 = tid & 15, f = tid >> 4;
                const float2* row = (const float2*)P +
                    ((size_t)(g * 16 + f) * 256 + slice) * 256;
#pragma unroll
                for (int j = 0; j < 8; j++) x[j] = row[n1 + 16 * j];
            } else {
                int f = tid & 15, n1 = tid >> 4;
                const __half2* src = g_mid + (size_t)slice * 128 * 128 + g * 16 + f;
#pragma unroll
                for (int j = 0; j < 8; j++)
                    x[j] = __half22float2(src[(size_t)(n1 + 16 * j) * 128]);
            }
            dft16_half(x, A);
        }
        // twiddle W256^(n1*k1) + transpose store (phase-1 n1 differs by mode)
        {
            int n1 = (fft_mode == 1) ? (tid & 15) : (tid >> 4);
            int f  = (fft_mode == 1) ? (tid >> 4) : (tid & 15);
            float sn, cs;
            sincosf(PI_F * (float)n1 / 128.f, &sn, &cs);   // exp(+i*2pi*n1/256)
            float2 base = make_float2(cs, sn), w = make_float2(1.f, 0.f);
            float2* tp = sbuf + f * 273 + n1;
#pragma unroll
            for (int k1 = 0; k1 < 16; k1++) {
                tp[k1 * 17] = cmul(A[k1], w);
                w = cmul(w, base);
            }
        }
        __syncthreads();

        // --- phase 2: f2-fastest (channel-contiguous output) ---
        int f2 = tid & 15, t2 = tid >> 4;
        float2 c[16];
        const float2* rp = sbuf + f2 * 273 + t2 * 17;
#pragma unroll
        for (int i = 0; i < 16; i++) c[i] = rp[i];

        float2 X[16];
        dft16_full(c, X);

        if (fft_mode == 1) {
            // g_mid layout [x][ky][ch]; X[k2] -> x-pos t2 + 16*k2
            __half2* dst = g_mid + ((size_t)t2 * 128 + slice) * 128 + g * 16 + f2;
#pragma unroll
            for (int k2 = 0; k2 < 16; k2++)
                dst[(size_t)(16 * k2) * 128 * 128] = __floats2half2_rn(X[k2].x, X[k2].y);
        } else {
            // g_feat[fw] as half2: ((y*256+xcol)*128 + ch); X[k2] -> y = t2+16*k2
            __half2* dst = (__half2*)g_feat[fw] +
                           ((size_t)t2 * 256 + slice) * 128 + g * 16 + f2;
#pragma unroll
            for (int k2 = 0; k2 < 16; k2++)
                dst[(size_t)(16 * k2) * 256 * 128] = __floats2half2_rn(X[k2].x, X[k2].y);
        }
        return;
    }

    // ===================== Sampler role (R12 body) =====================
    int wl = ((int)blockIdx.x - fft_nblk) * 8 + (tid >> 5);
    if (wl >= samp_npts) return;
    int pt = samp_base + wl;
    int lane = tid & 31;

    float gx = __ldg(inputs + pt * 3 + ix);
    float gy = __ldg(inputs + pt * 3 + iy);
    float ic = __ldg(inputs + pt * 3 + is);

    float xx = (gx + 1.f) * 127.5f;
    float yy = (gy + 1.f) * 127.5f;
    float xf = floorf(xx), yf = floorf(yy);
    float wx = xx - xf, wy = yy - yf;
    int x0 = min(max((int)xf, 0), 255);
    int x1 = min(x0 + 1, 255);
    int y0 = min(max((int)yf, 0), 255);
    int y1 = min(y0 + 1, 255);
    __half2 w00 = __float2half2_rn((1.f - wx) * (1.f - wy));
    __half2 w01 = __float2half2_rn(wx * (1.f - wy));
    __half2 w10 = __float2half2_rn((1.f - wx) * wy);
    __half2 w11 = __float2half2_rn(wx * wy);

    const __half* fb = g_feat[fr];
    int co = lane << 3;
    uint4 u00 = __ldg((const uint4*)(fb + ((((y0 << 8) + x0) << 8) + co)));
    uint4 u01 = __ldg((const uint4*)(fb + ((((y0 << 8) + x1) << 8) + co)));
    uint4 u10 = __ldg((const uint4*)(fb + ((((y1 << 8) + x0) << 8) + co)));
    uint4 u11 = __ldg((const uint4*)(fb + ((((y1 << 8) + x1) << 8) + co)));
    const __half2* h00 = (const __half2*)&u00;
    const __half2* h01 = (const __half2*)&u01;
    const __half2* h10 = (const __half2*)&u10;
    const __half2* h11 = (const __half2*)&u11;

    float F[8];
#pragma unroll
    for (int k = 0; k < 4; k++) {
        __half2 a = __hfma2(w01, h01[k], __hmul2(w00, h00[k]));
        __half2 b = __hfma2(w11, h11[k], __hmul2(w10, h10[k]));
        float2 fa = __half22float2(a);
        float2 fb2 = __half22float2(b);
        F[2 * k]     = fa.x + fb2.x;
        F[2 * k + 1] = fa.y + fb2.y;
    }

    float s = (ic + 1.f) * 127.5f;
    float a = s * (PI_F / 128.f);
    bool re = (lane < 16);
    float sa  = re ? a : -a;
    float off = re ? (PI_F * 0.5f) : 0.f;
    float val = re ? F[0] : 0.f;
#pragma unroll
    for (int r = 1; r < 8; r++) {
        float th = fmaf((float)((1 << r) - 1), sa, off);
        val = fmaf(F[r], __sinf(th), val);
    }
    val += __shfl_down_sync(0xffffffffu, val, 16);
    if (lane < 16) {
        float v = val * (1.f / 65536.f);
        float* o = out + pt * CHOUT + lane;
        if (accum) *o += v; else *o = v;
    }
}

// ---------------------------------------------------------------------------
// Schedule: FFT of plane p+1 overlapped with sampling of plane p (halves).
//   L1 fftx(0) | L2 ffty(0)->feat0 | L3 fftx(1)+smp(0,A) | L4 ffty(1)->feat1+smp(0,B)
//   L5 fftx(2)+smp(1,A) | L6 ffty(2)->feat0+smp(1,B) | L7 smp(2) on feat0
// Sequential graph launches protect g_mid (x-pass p+1 only starts after
// y-pass p consumed it) and the feat ping-pong.
// ---------------------------------------------------------------------------
#define FX 1024              // fftx blocks: 8 groups x 128 rows
#define FY 2048              // ffty blocks: 8 groups x 256 cols
#define SH (HPTS / 8)        // sampler blocks for half the points

extern "C" void kernel_launch(void* const* d_in, const int* in_sizes, int n_in,
                              void* d_out, int out_size) {
    const float* P0 = (const float*)d_in[0];
    const float* P1 = (const float*)d_in[1];
    const float* P2 = (const float*)d_in[2];
    const float* inp = (const float*)d_in[3];
    float* out = (float*)d_out;
    // Plane (gx, gy, s) selectors: Pu {1,2,0}, Pv {0,2,1}, Pw {0,1,2}

    kslot<<<FX, 256>>>(P0, 1, FX, 0, 0, inp, out, 0, 0, 0, 0, 0, 0);
    kslot<<<FY, 256>>>(nullptr, 2, FY, 0, 0, inp, out, 0, 0, 0, 0, 0, 0);
    kslot<<<FX + SH, 256>>>(P1, 1, FX, 0, 0, inp, out, 1, 2, 0, 0, 0, HPTS);
    kslot<<<FY + SH, 256>>>(nullptr, 2, FY, 1, 0, inp, out, 1, 2, 0, 0, HPTS, HPTS);
    kslot<<<FX + SH, 256>>>(P2, 1, FX, 0, 1, inp, out, 0, 2, 1, 1, 0, HPTS);
    kslot<<<FY + SH, 256>>>(nullptr, 2, FY, 0, 1, inp, out, 0, 2, 1, 1, HPTS, HPTS);
    kslot<<<2 * SH, 256>>>(nullptr, 0, 0, 0, 0, inp, out, 0, 1, 2, 1, 0, NPTS);
}

// round 14
// speedup vs baseline: 1.4663x; 1.4663x over previous
#include <cuda_runtime.h>
#include <cuda_fp16.h>

#define RES     256
#define CHOUT   16
#define NCH     128          // CH*RR phasor channels per plane
#define NPTS    262144
#define PI_F    3.14159265358979323846f

// Scratch (device globals: allocation-free rule)
// g_mid[p]: [x][ky][ch] (x<256, ky<128, ch<128), complex fp16, 3 x 16.7 MB
__device__ __half2 g_mid[3][256 * 128 * NCH];
// g_feat[p]: [y][x][256ch] fp16 unnormalized, 3 x 33.5 MB
__device__ __half  g_feat[3][RES * RES * 2 * NCH];

__device__ __forceinline__ float2 cadd(float2 a, float2 b) { return make_float2(a.x + b.x, a.y + b.y); }
__device__ __forceinline__ float2 csub(float2 a, float2 b) { return make_float2(a.x - b.x, a.y - b.y); }
__device__ __forceinline__ float2 cmul(float2 a, float2 b) {
    return make_float2(fmaf(a.x, b.x, -a.y * b.y), fmaf(a.x, b.y, a.y * b.x));
}
__device__ __forceinline__ float2 muli(float2 a) { return make_float2(-a.y, a.x); }

// ===========================================================================
// Register DFT-16 (inverse, +i), radix-4 x radix-4, natural-order output.
// (verbatim from R12)
// ===========================================================================
__device__ __forceinline__ float2 w16m(int k) {
    const float C1 = 0.9238795325112867f, S1 = 0.3826834323650898f;
    const float C2 = 0.7071067811865476f;
    switch (k) {
        case 0:  return make_float2( 1.f, 0.f);
        case 1:  return make_float2( C1,  S1);
        case 2:  return make_float2( C2,  C2);
        case 3:  return make_float2( S1,  C1);
        case 4:  return make_float2( 0.f, 1.f);
        case 6:  return make_float2(-C2,  C2);
        default: return make_float2(-C1, -S1);     // case 9
    }
}

__device__ __forceinline__ void dft4i(float2& x0, float2& x1, float2& x2, float2& x3) {
    float2 a = cadd(x0, x2), b = csub(x0, x2);
    float2 c = cadd(x1, x3), d = muli(csub(x1, x3));
    x0 = cadd(a, c); x1 = cadd(b, d); x2 = csub(a, c); x3 = csub(b, d);
}

__device__ __forceinline__ void dft16_tail(float2 d[16], float2 out[16]) {
#pragma unroll
    for (int m = 0; m < 4; m++) {
        float2 e0 = d[0 + 4 * m];
        float2 e1 = cmul(d[1 + 4 * m], w16m(1 * m));
        float2 e2 = cmul(d[2 + 4 * m], w16m(2 * m));
        float2 e3 = cmul(d[3 + 4 * m], w16m(3 * m));
        float2 A = cadd(e0, e2), B = csub(e0, e2);
        float2 C = cadd(e1, e3), D = muli(csub(e1, e3));
        out[m]      = cadd(A, C);
        out[m + 4]  = cadd(B, D);
        out[m + 8]  = csub(A, C);
        out[m + 12] = csub(B, D);
    }
}

__device__ __forceinline__ void dft16_full(float2 x[16], float2 out[16]) {
#pragma unroll
    for (int a = 0; a < 4; a++) dft4i(x[a], x[a + 4], x[a + 8], x[a + 12]);
    dft16_tail(x, out);
}

__device__ __forceinline__ void dft16_half(const float2 x[8], float2 out[16]) {
    float2 d[16];
#pragma unroll
    for (int a = 0; a < 4; a++) {
        float2 u = x[a], v = x[a + 4];
        float2 iv = muli(v);
        d[a]      = cadd(u, v);
        d[a + 4]  = cadd(u, iv);
        d[a + 8]  = csub(u, v);
        d[a + 12] = csub(u, iv);
    }
    dft16_tail(d, out);
}

// ===========================================================================
// FFT kernels (R12 bodies, z-batched over the 3 planes).
// 16 threads per 256-pt IFFT, 16 FFTs/block, one smem transpose round.
// ===========================================================================

// x-pass: grid (NCH/16, 128, 3).
__global__ void __launch_bounds__(256)
kfftx3(const float* __restrict__ P0, const float* __restrict__ P1,
       const float* __restrict__ P2) {
    __shared__ float2 sbuf[16 * 273];              // 34.9 KB
    int tid = threadIdx.x, g = blockIdx.x, ky = blockIdx.y, pl = blockIdx.z;
    const float* P = (pl == 0) ? P0 : (pl == 1) ? P1 : P2;

    // phase 1: n1-fastest (coalesced 128B row reads)
    int n1 = tid & 15, f = tid >> 4;
    const float2* row = (const float2*)P + ((size_t)(g * 16 + f) * 256 + ky) * 256;
    float2 x[8];
#pragma unroll
    for (int j = 0; j < 8; j++) x[j] = row[n1 + 16 * j];

    float2 A[16];
    dft16_half(x, A);

    float sn, cs;
    sincosf(PI_F * (float)n1 / 128.f, &sn, &cs);   // exp(+i*2pi*n1/256)
    float2 base = make_float2(cs, sn), w = make_float2(1.f, 0.f);
    float2* tp = sbuf + f * 273 + n1;
#pragma unroll
    for (int k1 = 0; k1 < 16; k1++) {
        tp[k1 * 17] = cmul(A[k1], w);
        w = cmul(w, base);
    }
    __syncthreads();

    // phase 2: f2-fastest (channel-contiguous output)
    int f2 = tid & 15, t2 = tid >> 4;
    float2 c[16];
    const float2* rp = sbuf + f2 * 273 + t2 * 17;
#pragma unroll
    for (int i = 0; i < 16; i++) c[i] = rp[i];

    float2 X[16];
    dft16_full(c, X);                              // X[k2] -> x-pos t2 + 16*k2

    __half2* dst = g_mid[pl] + ((size_t)t2 * 128 + ky) * 128 + g * 16 + f2;
#pragma unroll
    for (int k2 = 0; k2 < 16; k2++)
        dst[(size_t)(16 * k2) * 128 * 128] = __floats2half2_rn(X[k2].x, X[k2].y);
}

// y-pass: grid (NCH/16, 256, 3).
__global__ void __launch_bounds__(256) kffty3() {
    __shared__ float2 sbuf[16 * 273];
    int tid = threadIdx.x, g = blockIdx.x, xcol = blockIdx.y, pl = blockIdx.z;

    // phase 1: f-fastest (channel-contiguous input, 64B chunks)
    int f = tid & 15, n1 = tid >> 4;
    const __half2* src = g_mid[pl] + (size_t)xcol * 128 * 128 + g * 16 + f;
    float2 x[8];
#pragma unroll
    for (int j = 0; j < 8; j++)
        x[j] = __half22float2(src[(size_t)(n1 + 16 * j) * 128]);

    float2 A[16];
    dft16_half(x, A);

    float sn, cs;
    sincosf(PI_F * (float)n1 / 128.f, &sn, &cs);
    float2 base = make_float2(cs, sn), w = make_float2(1.f, 0.f);
    float2* tp = sbuf + f * 273 + n1;
#pragma unroll
    for (int k1 = 0; k1 < 16; k1++) {
        tp[k1 * 17] = cmul(A[k1], w);
        w = cmul(w, base);
    }
    __syncthreads();

    // phase 2: f2-fastest (channel-contiguous feat output)
    int f2 = tid & 15, t2 = tid >> 4;
    float2 c[16];
    const float2* rp = sbuf + f2 * 273 + t2 * 17;
#pragma unroll
    for (int i = 0; i < 16; i++) c[i] = rp[i];

    float2 X[16];
    dft16_full(c, X);                              // X[k2] -> y-pos t2 + 16*k2

    __half2* dst = (__half2*)g_feat[pl] + ((size_t)t2 * 256 + xcol) * 128 + g * 16 + f2;
#pragma unroll
    for (int k2 = 0; k2 < 16; k2++)
        dst[(size_t)(16 * k2) * 256 * 128] = __floats2half2_rn(X[k2].x, X[k2].y);
}

// ===========================================================================
// Fused sampler: one warp per point; loops the 3 planes in-register and
// writes out ONCE (no accumulate RMW passes). Per-plane math is the R12
// sampler body verbatim.
// ===========================================================================
__global__ void __launch_bounds__(256)
ksample3(const float* __restrict__ inputs, float* __restrict__ out) {
    int warp = (blockIdx.x * blockDim.x + threadIdx.x) >> 5;
    int lane = threadIdx.x & 31;
    if (warp >= NPTS) return;

    float i0 = __ldg(inputs + warp * 3 + 0);
    float i1 = __ldg(inputs + warp * 3 + 1);
    float i2 = __ldg(inputs + warp * 3 + 2);

    int co = lane << 3;
    bool re = (lane < 16);
    float off = re ? (PI_F * 0.5f) : 0.f;
    float val = 0.f;

#pragma unroll
    for (int pl = 0; pl < 3; pl++) {
        float gx, gy, ic;
        if (pl == 0)      { gx = i1; gy = i2; ic = i0; }   // Pu
        else if (pl == 1) { gx = i0; gy = i2; ic = i1; }   // Pv
        else              { gx = i0; gy = i1; ic = i2; }   // Pw

        float xx = (gx + 1.f) * 127.5f;
        float yy = (gy + 1.f) * 127.5f;
        float xf = floorf(xx), yf = floorf(yy);
        float wx = xx - xf, wy = yy - yf;
        int x0 = min(max((int)xf, 0), 255);
        int x1 = min(x0 + 1, 255);
        int y0 = min(max((int)yf, 0), 255);
        int y1 = min(y0 + 1, 255);
        __half2 w00 = __float2half2_rn((1.f - wx) * (1.f - wy));
        __half2 w01 = __float2half2_rn(wx * (1.f - wy));
        __half2 w10 = __float2half2_rn((1.f - wx) * wy);
        __half2 w11 = __float2half2_rn(wx * wy);

        const __half* fb = g_feat[pl];
        uint4 u00 = __ldg((const uint4*)(fb + ((((y0 << 8) + x0) << 8) + co)));
        uint4 u01 = __ldg((const uint4*)(fb + ((((y0 << 8) + x1) << 8) + co)));
        uint4 u10 = __ldg((const uint4*)(fb + ((((y1 << 8) + x0) << 8) + co)));
        uint4 u11 = __ldg((const uint4*)(fb + ((((y1 << 8) + x1) << 8) + co)));
        const __half2* h00 = (const __half2*)&u00;
        const __half2* h01 = (const __half2*)&u01;
        const __half2* h10 = (const __half2*)&u10;
        const __half2* h11 = (const __half2*)&u11;

        float F[8];
#pragma unroll
        for (int k = 0; k < 4; k++) {
            __half2 a = __hfma2(w01, h01[k], __hmul2(w00, h00[k]));
            __half2 b = __hfma2(w11, h11[k], __hmul2(w10, h10[k]));
            float2 fa = __half22float2(a);
            float2 fb2 = __half22float2(b);
            F[2 * k]     = fa.x + fb2.x;
            F[2 * k + 1] = fa.y + fb2.y;
        }

        // theta_r = a*(2^r - 1), a = pi*s/128; cos via sin(+pi/2), -sin via sin(-th)
        float s = (ic + 1.f) * 127.5f;
        float a = s * (PI_F / 128.f);
        float sa = re ? a : -a;
        if (re) val += F[0];                       // r=0: coef=0 -> cos=1, sin=0
#pragma unroll
        for (int r = 1; r < 8; r++) {
            float th = fmaf((float)((1 << r) - 1), sa, off);
            val = fmaf(F[r], __sinf(th), val);
        }
    }

    val += __shfl_down_sync(0xffffffffu, val, 16);
    if (lane < 16)
        out[warp * CHOUT + lane] = val * (1.f / 65536.f);  // deferred ifft2 norm
}

// ---------------------------------------------------------------------------
extern "C" void kernel_launch(void* const* d_in, const int* in_sizes, int n_in,
                              void* d_out, int out_size) {
    const float* P0 = (const float*)d_in[0];
    const float* P1 = (const float*)d_in[1];
    const float* P2 = (const float*)d_in[2];
    const float* inp = (const float*)d_in[3];
    float* out = (float*)d_out;

    kfftx3<<<dim3(NCH / 16, 128, 3), 256>>>(P0, P1, P2);
    kffty3<<<dim3(NCH / 16, 256, 3), 256>>>();
    ksample3<<<NPTS / 8, 256>>>(inp, out);
}

// round 17
// speedup vs baseline: 1.4707x; 1.0030x over previous
#include <cuda_runtime.h>
#include <cuda_fp16.h>

#define RES     256
#define CHOUT   16
#define NCH     128          // CH*RR phasor channels per plane
#define NPTS    262144
#define PI_F    3.14159265358979323846f

// Scratch (device globals: allocation-free rule)
// g_mid[p]: [x][ky][ch] (x<256, ky<128, ch<128), complex fp16, 3 x 16.7 MB
__device__ __half2 g_mid[3][256 * 128 * NCH];
// g_feat[p]: [y][x][256ch] fp16 unnormalized, 3 x 33.5 MB
__device__ __half  g_feat[3][RES * RES * 2 * NCH];

__device__ __forceinline__ float2 cadd(float2 a, float2 b) { return make_float2(a.x + b.x, a.y + b.y); }
__device__ __forceinline__ float2 csub(float2 a, float2 b) { return make_float2(a.x - b.x, a.y - b.y); }
__device__ __forceinline__ float2 cmul(float2 a, float2 b) {
    return make_float2(fmaf(a.x, b.x, -a.y * b.y), fmaf(a.x, b.y, a.y * b.x));
}
__device__ __forceinline__ float2 muli(float2 a) { return make_float2(-a.y, a.x); }

// ===========================================================================
// Register DFT-16 (inverse, +i), radix-4 x radix-4, natural-order output.
// (verbatim from R12)
// ===========================================================================
__device__ __forceinline__ float2 w16m(int k) {
    const float C1 = 0.9238795325112867f, S1 = 0.3826834323650898f;
    const float C2 = 0.7071067811865476f;
    switch (k) {
        case 0:  return make_float2( 1.f, 0.f);
        case 1:  return make_float2( C1,  S1);
        case 2:  return make_float2( C2,  C2);
        case 3:  return make_float2( S1,  C1);
        case 4:  return make_float2( 0.f, 1.f);
        case 6:  return make_float2(-C2,  C2);
        default: return make_float2(-C1, -S1);     // case 9
    }
}

__device__ __forceinline__ void dft4i(float2& x0, float2& x1, float2& x2, float2& x3) {
    float2 a = cadd(x0, x2), b = csub(x0, x2);
    float2 c = cadd(x1, x3), d = muli(csub(x1, x3));
    x0 = cadd(a, c); x1 = cadd(b, d); x2 = csub(a, c); x3 = csub(b, d);
}

__device__ __forceinline__ void dft16_tail(float2 d[16], float2 out[16]) {
#pragma unroll
    for (int m = 0; m < 4; m++) {
        float2 e0 = d[0 + 4 * m];
        float2 e1 = cmul(d[1 + 4 * m], w16m(1 * m));
        float2 e2 = cmul(d[2 + 4 * m], w16m(2 * m));
        float2 e3 = cmul(d[3 + 4 * m], w16m(3 * m));
        float2 A = cadd(e0, e2), B = csub(e0, e2);
        float2 C = cadd(e1, e3), D = muli(csub(e1, e3));
        out[m]      = cadd(A, C);
        out[m + 4]  = cadd(B, D);
        out[m + 8]  = csub(A, C);
        out[m + 12] = csub(B, D);
    }
}

__device__ __forceinline__ void dft16_full(float2 x[16], float2 out[16]) {
#pragma unroll
    for (int a = 0; a < 4; a++) dft4i(x[a], x[a + 4], x[a + 8], x[a + 12]);
    dft16_tail(x, out);
}

__device__ __forceinline__ void dft16_half(const float2 x[8], float2 out[16]) {
    float2 d[16];
#pragma unroll
    for (int a = 0; a < 4; a++) {
        float2 u = x[a], v = x[a + 4];
        float2 iv = muli(v);
        d[a]      = cadd(u, v);
        d[a + 4]  = cadd(u, iv);
        d[a + 8]  = csub(u, v);
        d[a + 12] = csub(u, iv);
    }
    dft16_tail(d, out);
}

// ===========================================================================
// FFT kernels (R12 bodies, z-batched over the 3 planes).
// 16 threads per 256-pt IFFT, 16 FFTs/block, one smem transpose round.
// ===========================================================================

// x-pass: grid (NCH/16, 128, 3).
__global__ void __launch_bounds__(256)
kfftx3(const float* __restrict__ P0, const float* __restrict__ P1,
       const float* __restrict__ P2) {
    __shared__ float2 sbuf[16 * 273];              // 34.9 KB
    int tid = threadIdx.x, g = blockIdx.x, ky = blockIdx.y, pl = blockIdx.z;
    const float* P = (pl == 0) ? P0 : (pl == 1) ? P1 : P2;

    // phase 1: n1-fastest (coalesced 128B row reads)
    int n1 = tid & 15, f = tid >> 4;
    const float2* row = (const float2*)P + ((size_t)(g * 16 + f) * 256 + ky) * 256;
    float2 x[8];
#pragma unroll
    for (int j = 0; j < 8; j++) x[j] = row[n1 + 16 * j];

    float2 A[16];
    dft16_half(x, A);

    float sn, cs;
    sincosf(PI_F * (float)n1 / 128.f, &sn, &cs);   // exp(+i*2pi*n1/256)
    float2 base = make_float2(cs, sn), w = make_float2(1.f, 0.f);
    float2* tp = sbuf + f * 273 + n1;
#pragma unroll
    for (int k1 = 0; k1 < 16; k1++) {
        tp[k1 * 17] = cmul(A[k1], w);
        w = cmul(w, base);
    }
    __syncthreads();

    // phase 2: f2-fastest (channel-contiguous output)
    int f2 = tid & 15, t2 = tid >> 4;
    float2 c[16];
    const float2* rp = sbuf + f2 * 273 + t2 * 17;
#pragma unroll
    for (int i = 0; i < 16; i++) c[i] = rp[i];

    float2 X[16];
    dft16_full(c, X);                              // X[k2] -> x-pos t2 + 16*k2

    __half2* dst = g_mid[pl] + ((size_t)t2 * 128 + ky) * 128 + g * 16 + f2;
#pragma unroll
    for (int k2 = 0; k2 < 16; k2++)
        dst[(size_t)(16 * k2) * 128 * 128] = __floats2half2_rn(X[k2].x, X[k2].y);
}

// y-pass: grid (NCH/16, 256, 3).
__global__ void __launch_bounds__(256) kffty3() {
    __shared__ float2 sbuf[16 * 273];
    int tid = threadIdx.x, g = blockIdx.x, xcol = blockIdx.y, pl = blockIdx.z;

    // phase 1: f-fastest (channel-contiguous input, 64B chunks)
    int f = tid & 15, n1 = tid >> 4;
    const __half2* src = g_mid[pl] + (size_t)xcol * 128 * 128 + g * 16 + f;
    float2 x[8];
#pragma unroll
    for (int j = 0; j < 8; j++)
        x[j] = __half22float2(src[(size_t)(n1 + 16 * j) * 128]);

    float2 A[16];
    dft16_half(x, A);

    float sn, cs;
    sincosf(PI_F * (float)n1 / 128.f, &sn, &cs);
    float2 base = make_float2(cs, sn), w = make_float2(1.f, 0.f);
    float2* tp = sbuf + f * 273 + n1;
#pragma unroll
    for (int k1 = 0; k1 < 16; k1++) {
        tp[k1 * 17] = cmul(A[k1], w);
        w = cmul(w, base);
    }
    __syncthreads();

    // phase 2: f2-fastest (channel-contiguous feat output)
    int f2 = tid & 15, t2 = tid >> 4;
    float2 c[16];
    const float2* rp = sbuf + f2 * 273 + t2 * 17;
#pragma unroll
    for (int i = 0; i < 16; i++) c[i] = rp[i];

    float2 X[16];
    dft16_full(c, X);                              // X[k2] -> y-pos t2 + 16*k2

    __half2* dst = (__half2*)g_feat[pl] + ((size_t)t2 * 256 + xcol) * 128 + g * 16 + f2;
#pragma unroll
    for (int k2 = 0; k2 < 16; k2++)
        dst[(size_t)(16 * k2) * 256 * 128] = __floats2half2_rn(X[k2].x, X[k2].y);
}

// ===========================================================================
// Fused sampler: one warp per point; loops the 3 planes in-register and
// writes out ONCE (no accumulate RMW passes). Per-plane math is the R12
// sampler body verbatim.
// ===========================================================================
__global__ void __launch_bounds__(256)
ksample3(const float* __restrict__ inputs, float* __restrict__ out) {
    int warp = (blockIdx.x * blockDim.x + threadIdx.x) >> 5;
    int lane = threadIdx.x & 31;
    if (warp >= NPTS) return;

    float i0 = __ldg(inputs + warp * 3 + 0);
    float i1 = __ldg(inputs + warp * 3 + 1);
    float i2 = __ldg(inputs + warp * 3 + 2);

    int co = lane << 3;
    bool re = (lane < 16);
    float off = re ? (PI_F * 0.5f) : 0.f;
    float val = 0.f;

#pragma unroll
    for (int pl = 0; pl < 3; pl++) {
        float gx, gy, ic;
        if (pl == 0)      { gx = i1; gy = i2; ic = i0; }   // Pu
        else if (pl == 1) { gx = i0; gy = i2; ic = i1; }   // Pv
        else              { gx = i0; gy = i1; ic = i2; }   // Pw

        float xx = (gx + 1.f) * 127.5f;
        float yy = (gy + 1.f) * 127.5f;
        float xf = floorf(xx), yf = floorf(yy);
        float wx = xx - xf, wy = yy - yf;
        int x0 = min(max((int)xf, 0), 255);
        int x1 = min(x0 + 1, 255);
        int y0 = min(max((int)yf, 0), 255);
        int y1 = min(y0 + 1, 255);
        __half2 w00 = __float2half2_rn((1.f - wx) * (1.f - wy));
        __half2 w01 = __float2half2_rn(wx * (1.f - wy));
        __half2 w10 = __float2half2_rn((1.f - wx) * wy);
        __half2 w11 = __float2half2_rn(wx * wy);

        const __half* fb = g_feat[pl];
        uint4 u00 = __ldg((const uint4*)(fb + ((((y0 << 8) + x0) << 8) + co)));
        uint4 u01 = __ldg((const uint4*)(fb + ((((y0 << 8) + x1) << 8) + co)));
        uint4 u10 = __ldg((const uint4*)(fb + ((((y1 << 8) + x0) << 8) + co)));
        uint4 u11 = __ldg((const uint4*)(fb + ((((y1 << 8) + x1) << 8) + co)));
        const __half2* h00 = (const __half2*)&u00;
        const __half2* h01 = (const __half2*)&u01;
        const __half2* h10 = (const __half2*)&u10;
        const __half2* h11 = (const __half2*)&u11;

        float F[8];
#pragma unroll
        for (int k = 0; k < 4; k++) {
            __half2 a = __hfma2(w01, h01[k], __hmul2(w00, h00[k]));
            __half2 b = __hfma2(w11, h11[k], __hmul2(w10, h10[k]));
            float2 fa = __half22float2(a);
            float2 fb2 = __half22float2(b);
            F[2 * k]     = fa.x + fb2.x;
            F[2 * k + 1] = fa.y + fb2.y;
        }

        // theta_r = a*(2^r - 1), a = pi*s/128; cos via sin(+pi/2), -sin via sin(-th)
        float s = (ic + 1.f) * 127.5f;
        float a = s * (PI_F / 128.f);
        float sa = re ? a : -a;
        if (re) val += F[0];                       // r=0: coef=0 -> cos=1, sin=0
#pragma unroll
        for (int r = 1; r < 8; r++) {
            float th = fmaf((float)((1 << r) - 1), sa, off);
            val = fmaf(F[r], __sinf(th), val);
        }
    }

    val += __shfl_down_sync(0xffffffffu, val, 16);
    if (lane < 16)
        out[warp * CHOUT + lane] = val * (1.f / 65536.f);  // deferred ifft2 norm
}

// ---------------------------------------------------------------------------
extern "C" void kernel_launch(void* const* d_in, const int* in_sizes, int n_in,
                              void* d_out, int out_size) {
    const float* P0 = (const float*)d_in[0];
    const float* P1 = (const float*)d_in[1];
    const float* P2 = (const float*)d_in[2];
    const float* inp = (const float*)d_in[3];
    float* out = (float*)d_out;

    kfftx3<<<dim3(NCH / 16, 128, 3), 256>>>(P0, P1, P2);
    kffty3<<<dim3(NCH / 16, 256, 3), 256>>>();
    ksample3<<<NPTS / 8, 256>>>(inp, out);
}